// round 8
// baseline (speedup 1.0000x reference)
#include <cuda_runtime.h>
#include <cuda_bf16.h>
#include <math.h>

// Problem constants (from reference setup_inputs)
#define N 8192
#define D 128
#define MARGIN 0.3f

// Scratch (device globals -- allocation-free per harness rules)
__device__ float        g_sq[N];
__device__ unsigned int g_ap[N];   // float bits of hard-positive max (all dists >= 0)
__device__ unsigned int g_an[N];   // float bits of hard-negative min

// ---------------------------------------------------------------------------
// Kernel 1: row squared norms + init of ap/an scratch. One warp per row.
// ---------------------------------------------------------------------------
__global__ void sqnorm_kernel(const float* __restrict__ x) {
    int warp = (blockIdx.x * blockDim.x + threadIdx.x) >> 5;
    int lane = threadIdx.x & 31;
    if (warp >= N) return;
    const float4* xr = reinterpret_cast<const float4*>(x + (size_t)warp * D);
    float4 v = xr[lane];                       // 32 lanes x 4 = 128 elems
    float s = v.x * v.x + v.y * v.y + v.z * v.z + v.w * v.w;
    #pragma unroll
    for (int o = 16; o > 0; o >>= 1) s += __shfl_xor_sync(0xffffffffu, s, o);
    if (lane == 0) {
        g_sq[warp] = s;
        g_ap[warp] = 0u;            // 0.0f (diag always contributes dist 0)
        g_an[warp] = 0x7f800000u;   // +inf
    }
}

// ---------------------------------------------------------------------------
// Kernel 2: 64x64 distance tiles. 16x16 threads, 4x4 outputs per thread,
// k-chunks of 16 via float4 loads (X lives in L2: only 4 MB).
// Epilogue: dist = sqrt(max(sqi+sqj-2dot,0)); store; masked max/min reduce.
// ---------------------------------------------------------------------------
__global__ __launch_bounds__(256, 4)
void dist_kernel(const float* __restrict__ x, const int* __restrict__ tgt,
                 float* __restrict__ out) {
    __shared__ float As[16][64];
    __shared__ float Bs[16][64];
    __shared__ unsigned int sAp[64];
    __shared__ unsigned int sAn[64];

    const int tx = threadIdx.x;            // 0..15 -> cols
    const int ty = threadIdx.y;            // 0..15 -> rows
    const int t  = ty * 16 + tx;           // 0..255
    const int iBase = blockIdx.y * 64;
    const int jBase = blockIdx.x * 64;

    if (t < 64) { sAp[t] = 0u; sAn[t] = 0x7f800000u; }

    // load indices for the cooperative tile fill: 64 rows x 16 k per chunk
    const int lr = t >> 2;                 // 0..63
    const int lk = (t & 3) * 4;            // 0,4,8,12

    float acc[4][4];
    #pragma unroll
    for (int r = 0; r < 4; r++)
        #pragma unroll
        for (int c = 0; c < 4; c++) acc[r][c] = 0.f;

    #pragma unroll
    for (int kc = 0; kc < D; kc += 16) {
        float4 av = *reinterpret_cast<const float4*>(x + (size_t)(iBase + lr) * D + kc + lk);
        float4 bv = *reinterpret_cast<const float4*>(x + (size_t)(jBase + lr) * D + kc + lk);
        __syncthreads();                    // protect previous iteration reads
        As[lk + 0][lr] = av.x; As[lk + 1][lr] = av.y;
        As[lk + 2][lr] = av.z; As[lk + 3][lr] = av.w;
        Bs[lk + 0][lr] = bv.x; Bs[lk + 1][lr] = bv.y;
        Bs[lk + 2][lr] = bv.z; Bs[lk + 3][lr] = bv.w;
        __syncthreads();

        #pragma unroll
        for (int kk = 0; kk < 16; kk++) {
            float a[4], b[4];
            #pragma unroll
            for (int r = 0; r < 4; r++) a[r] = As[kk][ty * 4 + r];
            #pragma unroll
            for (int c = 0; c < 4; c++) b[c] = Bs[kk][tx * 4 + c];
            #pragma unroll
            for (int r = 0; r < 4; r++)
                #pragma unroll
                for (int c = 0; c < 4; c++) acc[r][c] = fmaf(a[r], b[c], acc[r][c]);
        }
    }

    // epilogue
    float sqi[4], sqj[4], apv[4], anv[4];
    int ti[4], tj[4];
    #pragma unroll
    for (int r = 0; r < 4; r++) {
        int row = iBase + ty * 4 + r;
        sqi[r] = g_sq[row];
        ti[r]  = tgt[row];
        apv[r] = 0.f;
        anv[r] = __int_as_float(0x7f800000);   // +inf
    }
    #pragma unroll
    for (int c = 0; c < 4; c++) {
        int col = jBase + tx * 4 + c;
        sqj[c] = g_sq[col];
        tj[c]  = tgt[col];
    }

    #pragma unroll
    for (int r = 0; r < 4; r++) {
        int row = iBase + ty * 4 + r;
        float* orow = out + (size_t)row * N + jBase + tx * 4;
        #pragma unroll
        for (int c = 0; c < 4; c++) {
            float sqd = sqi[r] + sqj[c] - 2.f * acc[r][c];
            float dd  = (sqd > 0.f) ? sqrtf(sqd) : 0.f;
            orow[c] = dd;
            if (ti[r] == tj[c]) apv[r] = fmaxf(apv[r], dd);
            else                anv[r] = fminf(anv[r], dd);
        }
    }

    __syncthreads();   // sAp/sAn init done (and smem tile reads finished)
    #pragma unroll
    for (int r = 0; r < 4; r++) {
        atomicMax(&sAp[ty * 4 + r], __float_as_uint(apv[r]));
        atomicMin(&sAn[ty * 4 + r], __float_as_uint(anv[r]));
    }
    __syncthreads();
    if (t < 64) {
        atomicMax(&g_ap[iBase + t], sAp[t]);
        atomicMin(&g_an[iBase + t], sAn[t]);
    }
}

// ---------------------------------------------------------------------------
// Kernel 3: loss = mean(relu(ap - an + margin)). Single block.
// ---------------------------------------------------------------------------
__global__ void loss_kernel(float* __restrict__ out) {
    __shared__ float red[32];
    float s = 0.f;
    for (int i = threadIdx.x; i < N; i += blockDim.x) {
        float ap = __uint_as_float(g_ap[i]);
        float an = __uint_as_float(g_an[i]);
        float v  = ap - an + MARGIN;
        s += (v > 0.f) ? v : 0.f;
    }
    #pragma unroll
    for (int o = 16; o > 0; o >>= 1) s += __shfl_xor_sync(0xffffffffu, s, o);
    int lane = threadIdx.x & 31, wid = threadIdx.x >> 5;
    if (lane == 0) red[wid] = s;
    __syncthreads();
    if (wid == 0) {
        s = (lane < (blockDim.x >> 5)) ? red[lane] : 0.f;
        #pragma unroll
        for (int o = 16; o > 0; o >>= 1) s += __shfl_xor_sync(0xffffffffu, s, o);
        if (lane == 0) out[0] = s / (float)N;
    }
}

// ---------------------------------------------------------------------------
extern "C" void kernel_launch(void* const* d_in, const int* in_sizes, int n_in,
                              void* d_out, int out_size) {
    const float* x   = (const float*)d_in[0];
    const int*   tgt = (const int*)d_in[1];
    float* out = (float*)d_out;           // out[0] = loss, out[1..] = dist

    // 1) row sq-norms + scratch init: 8 warps/block
    sqnorm_kernel<<<N / 8, 256>>>(x);

    // 2) distance tiles: 128x128 grid of 64x64 tiles
    dim3 grid(N / 64, N / 64), block(16, 16);
    dist_kernel<<<grid, block>>>(x, tgt, out + 1);

    // 3) loss reduction
    loss_kernel<<<1, 1024>>>(out);
}

// round 10
// speedup vs baseline: 3.6337x; 3.6337x over previous
#include <cuda_runtime.h>
#include <cuda_bf16.h>
#include <math.h>
#include <stdint.h>

// Problem constants
#define N 8192
#define D 128
#define MARGIN 0.3f
#define TILE 128
#define PITCH 136            // bf16 elems per smem tile row (128 + 8 pad)

// Scratch (device globals -- allocation-free per harness rules)
__device__ float        g_sq[N];
__device__ unsigned int g_ap[N];   // float bits of hard-positive max (dists >= 0)
__device__ unsigned int g_an[N];   // float bits of hard-negative min

// Dynamic smem layout (bytes)
#define SM_A     0
#define SM_B     (128 * PITCH * 2)               // 34816
#define SM_META  (2 * 128 * PITCH * 2)           // 69632
#define SM_SQB   (SM_META + 0)                   // float[128]
#define SM_TGB   (SM_META + 512)                 // int[128]
#define SM_SAP   (SM_META + 1024)                // uint[128]
#define SM_SAN   (SM_META + 1536)                // uint[128]
#define SM_TOTAL (SM_META + 2048)                // 71680
// Epilogue stage reuses [SM_A, SM_META): 8 warps x 32x66 floats (8448 B each)

__device__ __forceinline__ uint32_t smem_u32(const void* p) {
    uint32_t a;
    asm("{ .reg .u64 t; cvta.to.shared.u64 t, %1; cvt.u32.u64 %0, t; }"
        : "=r"(a) : "l"(p));
    return a;
}

__device__ __forceinline__ void ldmatrix_x4(uint32_t* r, uint32_t addr) {
    asm volatile("ldmatrix.sync.aligned.m8n8.x4.shared.b16 {%0,%1,%2,%3}, [%4];"
                 : "=r"(r[0]), "=r"(r[1]), "=r"(r[2]), "=r"(r[3]) : "r"(addr));
}

__device__ __forceinline__ void mma16816(float* c, const uint32_t* a,
                                         uint32_t b0, uint32_t b1) {
    asm volatile(
        "mma.sync.aligned.m16n8k16.row.col.f32.bf16.bf16.f32 "
        "{%0,%1,%2,%3}, {%4,%5,%6,%7}, {%8,%9}, {%0,%1,%2,%3};"
        : "+f"(c[0]), "+f"(c[1]), "+f"(c[2]), "+f"(c[3])
        : "r"(a[0]), "r"(a[1]), "r"(a[2]), "r"(a[3]), "r"(b0), "r"(b1));
}

// ---------------------------------------------------------------------------
// Kernel 1: row squared norms of the bf16-ROUNDED inputs (keeps the quadratic
// form consistent with the tensor-core dot) + ap/an init. One warp per row.
// ---------------------------------------------------------------------------
__global__ void sqnorm_kernel(const float* __restrict__ x) {
    int warp = (blockIdx.x * blockDim.x + threadIdx.x) >> 5;
    int lane = threadIdx.x & 31;
    if (warp >= N) return;
    const float4* xr = reinterpret_cast<const float4*>(x + (size_t)warp * D);
    float4 v = xr[lane];
    float a0 = __bfloat162float(__float2bfloat16_rn(v.x));
    float a1 = __bfloat162float(__float2bfloat16_rn(v.y));
    float a2 = __bfloat162float(__float2bfloat16_rn(v.z));
    float a3 = __bfloat162float(__float2bfloat16_rn(v.w));
    float s = a0 * a0 + a1 * a1 + a2 * a2 + a3 * a3;
    #pragma unroll
    for (int o = 16; o > 0; o >>= 1) s += __shfl_xor_sync(0xffffffffu, s, o);
    if (lane == 0) {
        g_sq[warp] = s;
        g_ap[warp] = 0u;
        g_an[warp] = 0x7f800000u;
    }
}

// ---------------------------------------------------------------------------
// Kernel 2: 128x128 distance tiles via mma.sync bf16 HMMA.
// 8 warps; warp w -> rows 32*(w&3), cols 64*(w>>2) of the tile.
// ---------------------------------------------------------------------------
__global__ __launch_bounds__(256)
void dist_kernel(const float* __restrict__ x, const int* __restrict__ tgt,
                 float* __restrict__ out) {
    extern __shared__ char smem[];
    const uint32_t sbase = smem_u32(smem);
    const int t    = threadIdx.x;
    const int lane = t & 31;
    const int wid  = t >> 5;
    const int iBase = blockIdx.y * TILE;
    const int jBase = blockIdx.x * TILE;

    float*    sqB = (float*)(smem + SM_SQB);
    int*      tgB = (int*)(smem + SM_TGB);
    unsigned* sAp = (unsigned*)(smem + SM_SAP);
    unsigned* sAn = (unsigned*)(smem + SM_SAN);

    if (t < 128) {
        sqB[t] = g_sq[jBase + t];
        tgB[t] = tgt[jBase + t];
        sAp[t] = 0u;
        sAn[t] = 0x7f800000u;
    }

    // Fill A (rows iBase..) and B (rows jBase..) bf16 tiles, pitch PITCH.
    {
        const float4* XA = reinterpret_cast<const float4*>(x + (size_t)iBase * D);
        const float4* XB = reinterpret_cast<const float4*>(x + (size_t)jBase * D);
        #pragma unroll
        for (int idx = t; idx < TILE * 32; idx += 256) {
            int row = idx >> 5, q = idx & 31;           // col = 4*q
            float4 a = XA[row * 32 + q];
            float4 b = XB[row * 32 + q];
            union { __nv_bfloat162 h[2]; uint2 u; } ua, ub;
            ua.h[0] = __floats2bfloat162_rn(a.x, a.y);
            ua.h[1] = __floats2bfloat162_rn(a.z, a.w);
            ub.h[0] = __floats2bfloat162_rn(b.x, b.y);
            ub.h[1] = __floats2bfloat162_rn(b.z, b.w);
            uint32_t off = (uint32_t)(row * PITCH + q * 4) * 2;
            *reinterpret_cast<uint2*>(smem + SM_A + off) = ua.u;
            *reinterpret_cast<uint2*>(smem + SM_B + off) = ub.u;
        }
    }
    __syncthreads();

    const int rw0 = (wid & 3) * 32;     // warp sub-tile row base (tile-local)
    const int cw0 = (wid >> 2) * 64;    // warp sub-tile col base (tile-local)

    float acc[2][8][4];
    #pragma unroll
    for (int mt = 0; mt < 2; mt++)
        #pragma unroll
        for (int nt = 0; nt < 8; nt++)
            #pragma unroll
            for (int e = 0; e < 4; e++) acc[mt][nt][e] = 0.f;

    const uint32_t aB  = sbase + SM_A;
    const uint32_t bB  = sbase + SM_B;
    const int lrow = lane & 15;
    const int koff = (lane >> 4) * 8;

    #pragma unroll
    for (int ks = 0; ks < 8; ks++) {
        const int k0 = ks * 16;
        uint32_t af[2][4];
        #pragma unroll
        for (int mt = 0; mt < 2; mt++)
            ldmatrix_x4(af[mt],
                aB + (uint32_t)((rw0 + 16 * mt + lrow) * PITCH + k0 + koff) * 2);
        uint32_t bf[4][4];
        #pragma unroll
        for (int ng = 0; ng < 4; ng++)
            ldmatrix_x4(bf[ng],
                bB + (uint32_t)((cw0 + 16 * ng + lrow) * PITCH + k0 + koff) * 2);
        #pragma unroll
        for (int mt = 0; mt < 2; mt++)
            #pragma unroll
            for (int ng = 0; ng < 4; ng++) {
                mma16816(acc[mt][2 * ng + 0], af[mt], bf[ng][0], bf[ng][2]);
                mma16816(acc[mt][2 * ng + 1], af[mt], bf[ng][1], bf[ng][3]);
            }
    }
    __syncthreads();   // all ldmatrix reads done -> A/B smem reusable as stage

    // Epilogue: dist + masked max/min + stage for coalesced store.
    float* stage = (float*)(smem + (size_t)wid * (32 * 66 * 4));  // < SM_META
    const int qr = lane >> 2;            // 0..7
    const int qc = 2 * (lane & 3);       // 0,2,4,6
    const float INF = __int_as_float(0x7f800000);

    #pragma unroll
    for (int mt = 0; mt < 2; mt++) {
        const int rl_lo = rw0 + 16 * mt + qr;      // tile-local rows
        const int rl_hi = rl_lo + 8;
        const int rg_lo = iBase + rl_lo;
        const int rg_hi = iBase + rl_hi;
        const float sq_lo = g_sq[rg_lo], sq_hi = g_sq[rg_hi];
        const int   tt_lo = tgt[rg_lo],  tt_hi = tgt[rg_hi];
        float ap_lo = 0.f, an_lo = INF, ap_hi = 0.f, an_hi = INF;

        #pragma unroll
        for (int nt = 0; nt < 8; nt++) {
            const int cl0 = cw0 + 8 * nt + qc;     // tile-local cols
            const float sc0 = sqB[cl0], sc1 = sqB[cl0 + 1];
            const int   tc0 = tgB[cl0], tc1 = tgB[cl0 + 1];
            const int   cg0 = jBase + cl0;

            float s00 = sq_lo + sc0 - 2.f * acc[mt][nt][0];
            float s01 = sq_lo + sc1 - 2.f * acc[mt][nt][1];
            float s10 = sq_hi + sc0 - 2.f * acc[mt][nt][2];
            float s11 = sq_hi + sc1 - 2.f * acc[mt][nt][3];
            float d00 = (s00 > 0.f) ? sqrtf(s00) : 0.f;
            float d01 = (s01 > 0.f) ? sqrtf(s01) : 0.f;
            float d10 = (s10 > 0.f) ? sqrtf(s10) : 0.f;
            float d11 = (s11 > 0.f) ? sqrtf(s11) : 0.f;
            if (rg_lo == cg0)     d00 = 0.f;       // exact diagonal, like ref
            if (rg_lo == cg0 + 1) d01 = 0.f;
            if (rg_hi == cg0)     d10 = 0.f;
            if (rg_hi == cg0 + 1) d11 = 0.f;

            if (tt_lo == tc0) ap_lo = fmaxf(ap_lo, d00); else an_lo = fminf(an_lo, d00);
            if (tt_lo == tc1) ap_lo = fmaxf(ap_lo, d01); else an_lo = fminf(an_lo, d01);
            if (tt_hi == tc0) ap_hi = fmaxf(ap_hi, d10); else an_hi = fminf(an_hi, d10);
            if (tt_hi == tc1) ap_hi = fmaxf(ap_hi, d11); else an_hi = fminf(an_hi, d11);

            const int sr = 16 * mt + qr;           // warp-slab-local row
            const int sc = 8 * nt + qc;            // warp-slab-local col
            stage[sr * 66 + sc]       = d00;
            stage[sr * 66 + sc + 1]   = d01;
            stage[(sr + 8) * 66 + sc]     = d10;
            stage[(sr + 8) * 66 + sc + 1] = d11;
        }

        // quad reduce (lanes 4r..4r+3 share the same rows)
        #pragma unroll
        for (int o = 1; o <= 2; o <<= 1) {
            ap_lo = fmaxf(ap_lo, __shfl_xor_sync(0xffffffffu, ap_lo, o));
            an_lo = fminf(an_lo, __shfl_xor_sync(0xffffffffu, an_lo, o));
            ap_hi = fmaxf(ap_hi, __shfl_xor_sync(0xffffffffu, ap_hi, o));
            an_hi = fminf(an_hi, __shfl_xor_sync(0xffffffffu, an_hi, o));
        }
        if ((lane & 3) == 0) {
            atomicMax(&sAp[rl_lo], __float_as_uint(ap_lo));
            atomicMin(&sAn[rl_lo], __float_as_uint(an_lo));
            atomicMax(&sAp[rl_hi], __float_as_uint(ap_hi));
            atomicMin(&sAn[rl_hi], __float_as_uint(an_hi));
        }
    }
    __syncwarp();

    // Coalesced stores of the warp's 32x64 sub-tile
    #pragma unroll
    for (int s = 0; s < 32; s++) {
        size_t base = (size_t)(iBase + rw0 + s) * N + jBase + cw0;
        out[base + lane]      = stage[s * 66 + lane];
        out[base + 32 + lane] = stage[s * 66 + 32 + lane];
    }

    __syncthreads();
    if (t < 128) {
        atomicMax(&g_ap[iBase + t], sAp[t]);
        atomicMin(&g_an[iBase + t], sAn[t]);
    }
}

// ---------------------------------------------------------------------------
// Kernel 3: loss = mean(relu(ap - an + margin)). Single block.
// ---------------------------------------------------------------------------
__global__ void loss_kernel(float* __restrict__ out) {
    __shared__ float red[32];
    float s = 0.f;
    for (int i = threadIdx.x; i < N; i += blockDim.x) {
        float ap = __uint_as_float(g_ap[i]);
        float an = __uint_as_float(g_an[i]);
        float v  = ap - an + MARGIN;
        s += (v > 0.f) ? v : 0.f;
    }
    #pragma unroll
    for (int o = 16; o > 0; o >>= 1) s += __shfl_xor_sync(0xffffffffu, s, o);
    int lane = threadIdx.x & 31, wid = threadIdx.x >> 5;
    if (lane == 0) red[wid] = s;
    __syncthreads();
    if (wid == 0) {
        s = (lane < (blockDim.x >> 5)) ? red[lane] : 0.f;
        #pragma unroll
        for (int o = 16; o > 0; o >>= 1) s += __shfl_xor_sync(0xffffffffu, s, o);
        if (lane == 0) out[0] = s / (float)N;
    }
}

// ---------------------------------------------------------------------------
extern "C" void kernel_launch(void* const* d_in, const int* in_sizes, int n_in,
                              void* d_out, int out_size) {
    const float* x   = (const float*)d_in[0];
    const int*   tgt = (const int*)d_in[1];
    float* out = (float*)d_out;           // out[0] = loss, out[1..] = dist

    // Idempotent, capture-safe (not a stream op); no static guards.
    cudaFuncSetAttribute(dist_kernel,
                         cudaFuncAttributeMaxDynamicSharedMemorySize, SM_TOTAL);

    sqnorm_kernel<<<N / 8, 256>>>(x);

    dim3 grid(N / TILE, N / TILE);
    dist_kernel<<<grid, 256, SM_TOTAL>>>(x, tgt, out + 1);

    loss_kernel<<<1, 1024>>>(out);
}

// round 11
// speedup vs baseline: 3.8832x; 1.0686x over previous
#include <cuda_runtime.h>
#include <cuda_bf16.h>
#include <math.h>
#include <stdint.h>

// Problem constants
#define N 8192
#define D 128
#define MARGIN 0.3f
#define TILE 128
#define PITCHB 272           // bytes per smem tile row (128 bf16 = 256B + 16B pad)

// Scratch (device globals -- allocation-free per harness rules)
__device__ float        g_sq[N];
__device__ unsigned int g_ap[N];     // float bits of hard-positive max
__device__ unsigned int g_an[N];     // float bits of hard-negative min
__device__ uint4        g_xb4[N * D * 2 / 16];   // bf16-rounded X, 16B chunks

// Dynamic smem layout (bytes)
#define SM_A     0
#define SM_B     (128 * PITCHB)                  // 34816
#define SM_META  (2 * 128 * PITCHB)              // 69632
#define SM_SQB   (SM_META + 0)                   // float[128]
#define SM_TGB   (SM_META + 512)                 // int[128]
#define SM_SAP   (SM_META + 1024)                // uint[128]
#define SM_SAN   (SM_META + 1536)                // uint[128]
#define SM_TOTAL (SM_META + 2048)                // 71680
// Epilogue stage reuses [0, SM_META): 8 warps x (32 rows x 68 floats) = 8x8704

__device__ __forceinline__ uint32_t smem_u32(const void* p) {
    uint32_t a;
    asm("{ .reg .u64 t; cvta.to.shared.u64 t, %1; cvt.u32.u64 %0, t; }"
        : "=r"(a) : "l"(p));
    return a;
}

__device__ __forceinline__ void cp_async16(uint32_t dst, const void* src) {
    asm volatile("cp.async.cg.shared.global [%0], [%1], 16;"
                 :: "r"(dst), "l"(src) : "memory");
}

__device__ __forceinline__ void ldmatrix_x4(uint32_t* r, uint32_t addr) {
    asm volatile("ldmatrix.sync.aligned.m8n8.x4.shared.b16 {%0,%1,%2,%3}, [%4];"
                 : "=r"(r[0]), "=r"(r[1]), "=r"(r[2]), "=r"(r[3]) : "r"(addr));
}

__device__ __forceinline__ void mma16816(float* c, const uint32_t* a,
                                         uint32_t b0, uint32_t b1) {
    asm volatile(
        "mma.sync.aligned.m16n8k16.row.col.f32.bf16.bf16.f32 "
        "{%0,%1,%2,%3}, {%4,%5,%6,%7}, {%8,%9}, {%0,%1,%2,%3};"
        : "+f"(c[0]), "+f"(c[1]), "+f"(c[2]), "+f"(c[3])
        : "r"(a[0]), "r"(a[1]), "r"(a[2]), "r"(a[3]), "r"(b0), "r"(b1));
}

// ---------------------------------------------------------------------------
// Kernel 1: bf16-round X into g_xb4, row squared norms of the ROUNDED values
// (consistent quadratic form), init ap/an. One warp per row.
// ---------------------------------------------------------------------------
__global__ void prep_kernel(const float* __restrict__ x) {
    int row  = (blockIdx.x * blockDim.x + threadIdx.x) >> 5;
    int lane = threadIdx.x & 31;
    if (row >= N) return;
    const float4* xr = reinterpret_cast<const float4*>(x + (size_t)row * D);
    float4 v = xr[lane];
    union { __nv_bfloat162 h[2]; uint2 u; } ub;
    ub.h[0] = __floats2bfloat162_rn(v.x, v.y);
    ub.h[1] = __floats2bfloat162_rn(v.z, v.w);
    reinterpret_cast<uint2*>(g_xb4)[row * 32 + lane] = ub.u;
    float a0 = __bfloat162float(__float2bfloat16_rn(v.x));
    float a1 = __bfloat162float(__float2bfloat16_rn(v.y));
    float a2 = __bfloat162float(__float2bfloat16_rn(v.z));
    float a3 = __bfloat162float(__float2bfloat16_rn(v.w));
    float s = a0 * a0 + a1 * a1 + a2 * a2 + a3 * a3;
    #pragma unroll
    for (int o = 16; o > 0; o >>= 1) s += __shfl_xor_sync(0xffffffffu, s, o);
    if (lane == 0) {
        g_sq[row] = s;
        g_ap[row] = 0u;
        g_an[row] = 0x7f800000u;
    }
}

// ---------------------------------------------------------------------------
// Kernel 2: 128x128 distance tiles via mma.sync bf16 HMMA.
// ---------------------------------------------------------------------------
__global__ __launch_bounds__(256, 2)
void dist_kernel(const int* __restrict__ tgt, float* __restrict__ out) {
    extern __shared__ char smem[];
    const uint32_t sbase = smem_u32(smem);
    const int t    = threadIdx.x;
    const int lane = t & 31;
    const int wid  = t >> 5;
    const int iBase = blockIdx.y * TILE;
    const int jBase = blockIdx.x * TILE;

    float*    sqB = (float*)(smem + SM_SQB);
    int*      tgB = (int*)(smem + SM_TGB);
    unsigned* sAp = (unsigned*)(smem + SM_SAP);
    unsigned* sAn = (unsigned*)(smem + SM_SAN);

    if (t < 128) {
        sqB[t] = g_sq[jBase + t];
        tgB[t] = tgt[jBase + t];
        sAp[t] = 0u;
        sAn[t] = 0x7f800000u;
    }

    // Tile fill via cp.async: 16B chunks of pre-rounded bf16 rows.
    // Each tile: 128 rows x 16 chunks = 2048 chunks; 8 per thread per tile.
    {
        #pragma unroll
        for (int it = 0; it < 8; it++) {
            int idx = t + it * 256;           // 0..2047
            int row = idx >> 4, l = idx & 15;
            cp_async16(sbase + SM_A + row * PITCHB + l * 16,
                       &g_xb4[(size_t)(iBase + row) * 16 + l]);
            cp_async16(sbase + SM_B + row * PITCHB + l * 16,
                       &g_xb4[(size_t)(jBase + row) * 16 + l]);
        }
        asm volatile("cp.async.commit_group;" ::: "memory");
        asm volatile("cp.async.wait_group 0;" ::: "memory");
    }
    __syncthreads();

    const int rw0 = (wid & 3) * 32;     // warp sub-tile row base (tile-local)
    const int cw0 = (wid >> 2) * 64;    // warp sub-tile col base (tile-local)

    float acc[2][8][4];
    #pragma unroll
    for (int mt = 0; mt < 2; mt++)
        #pragma unroll
        for (int nt = 0; nt < 8; nt++)
            #pragma unroll
            for (int e = 0; e < 4; e++) acc[mt][nt][e] = 0.f;

    const uint32_t aB  = sbase + SM_A;
    const uint32_t bB  = sbase + SM_B;
    const int lrow = lane & 15;
    const int koff = (lane >> 4) * 8;

    #pragma unroll
    for (int ks = 0; ks < 8; ks++) {
        const int k0 = ks * 16;
        uint32_t af[2][4];
        #pragma unroll
        for (int mt = 0; mt < 2; mt++)
            ldmatrix_x4(af[mt],
                aB + (uint32_t)(rw0 + 16 * mt + lrow) * PITCHB + (k0 + koff) * 2);
        uint32_t bf[4][4];
        #pragma unroll
        for (int ng = 0; ng < 4; ng++)
            ldmatrix_x4(bf[ng],
                bB + (uint32_t)(cw0 + 16 * ng + lrow) * PITCHB + (k0 + koff) * 2);
        #pragma unroll
        for (int mt = 0; mt < 2; mt++)
            #pragma unroll
            for (int ng = 0; ng < 4; ng++) {
                mma16816(acc[mt][2 * ng + 0], af[mt], bf[ng][0], bf[ng][2]);
                mma16816(acc[mt][2 * ng + 1], af[mt], bf[ng][1], bf[ng][3]);
            }
    }
    __syncthreads();   // ldmatrix reads done -> A/B smem reusable as stage

    // Epilogue. Stage layout: stage[r][c] holds dist for global col (c-1),
    // pitch 68 floats, so float4 reads at c=4k map to global cols 4k-1 (=3 mod 4)
    // exactly where the d_out+1 shift makes STG.128 legal.
    float* stage = (float*)(smem + (size_t)wid * 8704);
    const int qr = lane >> 2;            // 0..7
    const int qc = 2 * (lane & 3);       // 0,2,4,6
    const float INF = __int_as_float(0x7f800000);

    #pragma unroll
    for (int mt = 0; mt < 2; mt++) {
        const int rl_lo = rw0 + 16 * mt + qr;
        const int rl_hi = rl_lo + 8;
        const int rg_lo = iBase + rl_lo;
        const int rg_hi = iBase + rl_hi;
        const float sq_lo = g_sq[rg_lo], sq_hi = g_sq[rg_hi];
        const int   tt_lo = tgt[rg_lo],  tt_hi = tgt[rg_hi];
        float ap_lo = 0.f, an_lo = INF, ap_hi = 0.f, an_hi = INF;

        #pragma unroll
        for (int nt = 0; nt < 8; nt++) {
            const int cl0 = cw0 + 8 * nt + qc;
            const float sc0 = sqB[cl0], sc1 = sqB[cl0 + 1];
            const int   tc0 = tgB[cl0], tc1 = tgB[cl0 + 1];
            const int   cg0 = jBase + cl0;

            float s00 = sq_lo + sc0 - 2.f * acc[mt][nt][0];
            float s01 = sq_lo + sc1 - 2.f * acc[mt][nt][1];
            float s10 = sq_hi + sc0 - 2.f * acc[mt][nt][2];
            float s11 = sq_hi + sc1 - 2.f * acc[mt][nt][3];
            float d00 = (s00 > 0.f) ? sqrtf(s00) : 0.f;
            float d01 = (s01 > 0.f) ? sqrtf(s01) : 0.f;
            float d10 = (s10 > 0.f) ? sqrtf(s10) : 0.f;
            float d11 = (s11 > 0.f) ? sqrtf(s11) : 0.f;
            if (rg_lo == cg0)     d00 = 0.f;      // exact diagonal, like ref
            if (rg_lo == cg0 + 1) d01 = 0.f;
            if (rg_hi == cg0)     d10 = 0.f;
            if (rg_hi == cg0 + 1) d11 = 0.f;

            if (tt_lo == tc0) ap_lo = fmaxf(ap_lo, d00); else an_lo = fminf(an_lo, d00);
            if (tt_lo == tc1) ap_lo = fmaxf(ap_lo, d01); else an_lo = fminf(an_lo, d01);
            if (tt_hi == tc0) ap_hi = fmaxf(ap_hi, d10); else an_hi = fminf(an_hi, d10);
            if (tt_hi == tc1) ap_hi = fmaxf(ap_hi, d11); else an_hi = fminf(an_hi, d11);

            const int sr = 16 * mt + qr;          // warp-slab-local row
            const int sc = 8 * nt + qc + 1;       // shifted column (c = jloc+1)
            stage[sr * 68 + sc]           = d00;
            stage[sr * 68 + sc + 1]       = d01;
            stage[(sr + 8) * 68 + sc]     = d10;
            stage[(sr + 8) * 68 + sc + 1] = d11;
        }

        // quad reduce (lanes 4r..4r+3 share the same rows)
        #pragma unroll
        for (int o = 1; o <= 2; o <<= 1) {
            ap_lo = fmaxf(ap_lo, __shfl_xor_sync(0xffffffffu, ap_lo, o));
            an_lo = fminf(an_lo, __shfl_xor_sync(0xffffffffu, an_lo, o));
            ap_hi = fmaxf(ap_hi, __shfl_xor_sync(0xffffffffu, ap_hi, o));
            an_hi = fminf(an_hi, __shfl_xor_sync(0xffffffffu, an_hi, o));
        }
        if ((lane & 3) == 0) {
            atomicMax(&sAp[rl_lo], __float_as_uint(ap_lo));
            atomicMin(&sAn[rl_lo], __float_as_uint(an_lo));
            atomicMax(&sAp[rl_hi], __float_as_uint(ap_hi));
            atomicMin(&sAn[rl_hi], __float_as_uint(an_hi));
        }
    }
    __syncwarp();

    // Wide stores: per row, 15 x STG.128 covering global cols 3..62 of the
    // slab (alignment: (1 + 4k-1 + multiples of 4) % 4 == 0), plus 4 scalars
    // for cols {0,1,2,63}. 2 rows per iteration, lanes 0-14 / 16-30 active.
    {
        const size_t rowBase = (size_t)(iBase + rw0) * N + jBase + cw0;
        const int k = (lane & 15) + 1;            // 1..16, active if <= 15
        #pragma unroll
        for (int it = 0; it < 16; it++) {
            int row = it * 2 + (lane >> 4);
            if (k <= 15) {
                float4 v = *reinterpret_cast<float4*>(stage + row * 68 + 4 * k);
                *reinterpret_cast<float4*>(out + rowBase + (size_t)row * N + 4 * k - 1) = v;
            }
        }
        const int e  = lane & 3;
        const int jl = (e == 3) ? 63 : e;
        #pragma unroll
        for (int it = 0; it < 4; it++) {
            int row = (it * 32 + lane) >> 2;
            out[rowBase + (size_t)row * N + jl] = stage[row * 68 + jl + 1];
        }
    }

    __syncthreads();
    if (t < 128) {
        atomicMax(&g_ap[iBase + t], sAp[t]);
        atomicMin(&g_an[iBase + t], sAn[t]);
    }
}

// ---------------------------------------------------------------------------
// Kernel 3: loss = mean(relu(ap - an + margin)). Single block.
// ---------------------------------------------------------------------------
__global__ void loss_kernel(float* __restrict__ out) {
    __shared__ float red[32];
    float s = 0.f;
    for (int i = threadIdx.x; i < N; i += blockDim.x) {
        float ap = __uint_as_float(g_ap[i]);
        float an = __uint_as_float(g_an[i]);
        float v  = ap - an + MARGIN;
        s += (v > 0.f) ? v : 0.f;
    }
    #pragma unroll
    for (int o = 16; o > 0; o >>= 1) s += __shfl_xor_sync(0xffffffffu, s, o);
    int lane = threadIdx.x & 31, wid = threadIdx.x >> 5;
    if (lane == 0) red[wid] = s;
    __syncthreads();
    if (wid == 0) {
        s = (lane < (blockDim.x >> 5)) ? red[lane] : 0.f;
        #pragma unroll
        for (int o = 16; o > 0; o >>= 1) s += __shfl_xor_sync(0xffffffffu, s, o);
        if (lane == 0) out[0] = s / (float)N;
    }
}

// ---------------------------------------------------------------------------
extern "C" void kernel_launch(void* const* d_in, const int* in_sizes, int n_in,
                              void* d_out, int out_size) {
    const float* x   = (const float*)d_in[0];
    const int*   tgt = (const int*)d_in[1];
    float* out = (float*)d_out;           // out[0] = loss, out[1..] = dist

    cudaFuncSetAttribute(dist_kernel,
                         cudaFuncAttributeMaxDynamicSharedMemorySize, SM_TOTAL);

    prep_kernel<<<N / 8, 256>>>(x);

    dim3 grid(N / TILE, N / TILE);
    dist_kernel<<<grid, 256, SM_TOTAL>>>(tgt, out + 1);

    loss_kernel<<<1, 1024>>>(out);
}